// round 8
// baseline (speedup 1.0000x reference)
#include <cuda_runtime.h>
#include <math.h>

#define NN     576
#define MR     144
#define RD     15
#define EDGES  (MR * RD)        // 2160
#define BATCH  256
#define ITERS  3
#define TPB    576              // 4 threads per check row; 1 column per thread
#define QE     4                // max edges per quarter-thread (4+4+4+3)
#define MAXDEG 18               // column-degree bound

// Column indices of the 15 ones in each of the 144 rows of H.
__device__ int g_cols[EDGES];

// Prep: one block per row, 576 threads, one coalesced load each.
__global__ void ldpc_prep(const float* __restrict__ H) {
    __shared__ int woff[18];
    const int m = blockIdx.x;
    const int t = threadIdx.x;
    const int w = t >> 5, l = t & 31;

    const float v = H[m * NN + t];
    const unsigned mask = __ballot_sync(0xFFFFFFFFu, v == 1.0f);
    if (l == 0) woff[w] = __popc(mask);
    __syncthreads();
    if (w == 0) {
        int orig = (l < 18) ? woff[l] : 0;
        int c = orig;
        #pragma unroll
        for (int off = 1; off < 32; off <<= 1) {
            int x = __shfl_up_sync(0xFFFFFFFFu, c, off);
            if (l >= off) c += x;
        }
        if (l < 18) woff[l] = c - orig;
    }
    __syncthreads();
    if (v == 1.0f) {
        int pos = woff[w] + __popc(mask & ((1u << l) - 1u));
        g_cols[m * RD + pos] = t;
    }
}

// Decode: one block per batch element, 576 threads = 4 per check row.
// Quarters handle 4/4/4/3 edges; merge min1/min2/argmin/sign via 2 shfl_xor
// rounds. Each thread owns exactly ONE column (n = t) for the gather phase.
__global__ __launch_bounds__(TPB, 2)
void ldpc_decode_kernel(const float* __restrict__ r,
                        const float* __restrict__ alpha,
                        const float* __restrict__ beta,
                        float* __restrict__ out) {
    __shared__ float E_sh[MAXDEG * NN];   // transposed edge messages (41.5 KB)
    __shared__ float V[NN];               // posterior
    __shared__ int   fill[NN];            // fill counters -> degrees

    const int t   = threadIdx.x;
    const int row = t >> 2;               // 0..143 (quad t&~3 shares row)
    const int qh  = t & 3;                // quarter id 0..3
    const int b   = blockIdx.x;

    // Stage g_cols coalesced into the E region.
    int* cstg = (int*)E_sh;
    for (int e = t; e < EDGES; e += TPB) cstg[e] = g_cols[e];

    float a_[ITERS], bt_[ITERS];
    #pragma unroll
    for (int it = 0; it < ITERS; it++) { a_[it] = alpha[it]; bt_[it] = beta[it]; }

    // Owned column: n = t (perfect 1:1, coalesced everywhere).
    const float rc = r[b * NN + t];
    V[t]    = rc;
    fill[t] = 0;
    __syncthreads();   // staging + fill ready

    // This quarter's edges: j in [j0, j0+ne)
    const int j0 = qh * QE;                    // 0,4,8,12
    const int ne = (qh < 3) ? QE : (RD - 3 * QE);  // 4,4,4,3

    int cols[QE];
    #pragma unroll
    for (int jj = 0; jj < QE; jj++)
        cols[jj] = (jj < ne) ? cstg[row * RD + j0 + jj] : 0;
    __syncthreads();   // staging reads done; E region free

    // One-time slot assignment (unique slot within each column).
    int slot[QE];
    #pragma unroll
    for (int jj = 0; jj < QE; jj++) {
        if (jj < ne) {
            int q = atomicAdd(&fill[cols[jj]], 1);
            slot[jj] = q * NN + cols[jj];
        }
    }
    __syncthreads();

    const int cd = fill[t];

    float Eprev[QE];
    #pragma unroll
    for (int jj = 0; jj < QE; jj++) Eprev[jj] = 0.0f;

    #pragma unroll
    for (int it = 0; it < ITERS; it++) {
        const float a  = a_[it];
        const float bt = bt_[it];

        // ---- row phase (quarter): gather, sign XOR, min1/min2 over my edges ----
        float am[QE];
        unsigned sb[QE];
        unsigned sgn = 0u;
        #pragma unroll
        for (int jj = 0; jj < QE; jj++) {
            if (jj < ne) {
                float m = V[cols[jj]] - Eprev[jj];
                sb[jj] = __float_as_uint(m) & 0x80000000u;
                sgn   ^= sb[jj];
                am[jj] = fabsf(m);
            } else {
                sb[jj] = 0u;
                am[jj] = INFINITY;
            }
        }
        // local min1/min2/argmin over <=4 values (first-index tie-break)
        float m1 = INFINITY, m2 = INFINITY; int jm = j0;
        #pragma unroll
        for (int jj = 0; jj < QE; jj++) {
            if (am[jj] < m1) { m2 = m1; m1 = am[jj]; jm = j0 + jj; }
            else if (am[jj] < m2) { m2 = am[jj]; }
        }

        // ---- merge across the 4 quarters: rounds xor 1, xor 2 ----
        // Round 1: pair {q, q^1}. Lower-index quarter wins ties.
        {
            const float o1 = __shfl_xor_sync(0xFFFFFFFFu, m1, 1);
            const float o2 = __shfl_xor_sync(0xFFFFFFFFu, m2, 1);
            const int   oj = __shfl_xor_sync(0xFFFFFFFFu, jm, 1);
            const unsigned os = __shfl_xor_sync(0xFFFFFFFFu, sgn, 1);
            const bool mine = (qh & 1) ? (m1 < o1) : (m1 <= o1);
            const float n2 = mine ? fminf(m2, o1) : fminf(o2, m1);
            m1 = mine ? m1 : o1;
            jm = mine ? jm : oj;
            m2 = n2;
            sgn ^= os;
        }
        // Round 2: pair {p, p^2} (pairs {0,1} vs {2,3}).
        {
            const float o1 = __shfl_xor_sync(0xFFFFFFFFu, m1, 2);
            const float o2 = __shfl_xor_sync(0xFFFFFFFFu, m2, 2);
            const int   oj = __shfl_xor_sync(0xFFFFFFFFu, jm, 2);
            const unsigned os = __shfl_xor_sync(0xFFFFFFFFu, sgn, 2);
            const bool mine = (qh & 2) ? (m1 < o1) : (m1 <= o1);
            const float n2 = mine ? fminf(m2, o1) : fminf(o2, m1);
            m1 = mine ? m1 : o1;
            jm = mine ? jm : oj;
            m2 = n2;
            sgn ^= os;
        }

        const float mag1 = a * fmaxf(0.0f, m1 - bt);
        const float mag2 = a * fmaxf(0.0f, m2 - bt);

        // ---- emit my edges ----
        #pragma unroll
        for (int jj = 0; jj < QE; jj++) {
            if (jj < ne) {
                float mag = ((j0 + jj) == jm) ? mag2 : mag1;
                float e = __uint_as_float(__float_as_uint(mag) ^ (sgn ^ sb[jj]));
                Eprev[jj] = e;
                E_sh[slot[jj]] = e;
            }
        }
        __syncthreads();   // edges published; V reads done

        // ---- column phase: my single column, conflict-free ----
        float s = rc;
        for (int q = 0; q < cd; q++) s += E_sh[q * NN + t];
        if (it < ITERS - 1) {
            V[t] = s;
            __syncthreads();
        } else {
            out[b * NN + t] = s;   // coalesced final store
        }
    }
}

extern "C" void kernel_launch(void* const* d_in, const int* in_sizes, int n_in,
                              void* d_out, int out_size) {
    const float* r     = (const float*)d_in[0];   // (256, 576)
    const float* H     = (const float*)d_in[1];   // (144, 576)
    const float* alpha = (const float*)d_in[2];   // (3,)
    const float* beta  = (const float*)d_in[3];   // (3,)
    float* out = (float*)d_out;                   // (256, 576)

    ldpc_prep<<<MR, NN>>>(H);
    ldpc_decode_kernel<<<BATCH, TPB>>>(r, alpha, beta, out);
}

// round 9
// speedup vs baseline: 1.2041x; 1.2041x over previous
#include <cuda_runtime.h>
#include <math.h>

#define NN     576
#define MR     144
#define RD     15
#define EDGES  (MR * RD)        // 2160
#define BATCH  256
#define ITERS  3
#define CWPB   2                // codewords per block
#define TPC    288              // threads per codeword (2 per check row)
#define TPB    (CWPB * TPC)     // 576
#define HEDGE  8                // max edges per half-thread (8 + 7)
#define MAXDEG 18               // column-degree bound

// Per-codeword shared layout (bytes)
#define E_OFF   0
#define E_SZ    (MAXDEG * NN * 4)            // 41472
#define V_OFF   (E_OFF + E_SZ)               // 41472
#define V_SZ    (NN * 4)                     // 2304
#define F_OFF   (V_OFF + V_SZ)               // 43776
#define F_SZ    (NN * 4)                     // 2304
#define CW_SZ   (F_OFF + F_SZ)               // 46080
#define SMEM_BYTES (CWPB * CW_SZ)            // 92160

// Column indices of the 15 ones in each of the 144 rows of H.
__device__ int g_cols[EDGES];

// Prep: one block per row, 576 threads, one coalesced load each.
__global__ void ldpc_prep(const float* __restrict__ H) {
    __shared__ int woff[18];
    const int m = blockIdx.x;
    const int t = threadIdx.x;
    const int w = t >> 5, l = t & 31;

    const float v = H[m * NN + t];
    const unsigned mask = __ballot_sync(0xFFFFFFFFu, v == 1.0f);
    if (l == 0) woff[w] = __popc(mask);
    __syncthreads();
    if (w == 0) {
        int orig = (l < 18) ? woff[l] : 0;
        int c = orig;
        #pragma unroll
        for (int off = 1; off < 32; off <<= 1) {
            int x = __shfl_up_sync(0xFFFFFFFFu, c, off);
            if (l >= off) c += x;
        }
        if (l < 18) woff[l] = c - orig;
    }
    __syncthreads();
    if (v == 1.0f) {
        int pos = woff[w] + __popc(mask & ((1u << l) - 1u));
        g_cols[m * RD + pos] = t;
    }
}

__device__ __forceinline__ void cw_bar(int half) {
    // Named barrier per codeword half: ids 1 and 2, 288 threads each.
    asm volatile("bar.sync %0, %1;" :: "r"(half + 1), "r"(TPC) : "memory");
}

// Decode: one block = TWO independent codewords (576 threads, 288 each).
// Within a codeword: 2 threads per check row (8/7 edge split, shfl_xor(1)
// merge), 2 owned columns per thread. Named barriers keep the codeword
// halves fully decoupled. No shared atomics in the iteration loop.
__global__ __launch_bounds__(TPB, 1)
void ldpc_decode_kernel(const float* __restrict__ r,
                        const float* __restrict__ alpha,
                        const float* __restrict__ beta,
                        float* __restrict__ out) {
    extern __shared__ char sm[];

    const int t    = threadIdx.x;
    const int half = t / TPC;             // codeword slot in this block
    const int u    = t - half * TPC;      // 0..287 within codeword
    const int row  = u >> 1;              // 0..143
    const int hf   = u & 1;               // edge-split half
    const int b    = blockIdx.x * CWPB + half;

    float* E_sh = (float*)(sm + half * CW_SZ + E_OFF);
    float* V    = (float*)(sm + half * CW_SZ + V_OFF);
    int*   fill = (int*)  (sm + half * CW_SZ + F_OFF);

    float a_[ITERS], bt_[ITERS];
    #pragma unroll
    for (int it = 0; it < ITERS; it++) { a_[it] = alpha[it]; bt_[it] = beta[it]; }

    // Owned columns: n0 = u, n1 = u + 288 (coalesced within the codeword).
    const int n0 = u, n1 = u + TPC;
    const float rc0 = r[b * NN + n0];
    const float rc1 = r[b * NN + n1];
    V[n0] = rc0;  V[n1] = rc1;
    fill[n0] = 0; fill[n1] = 0;

    // This half's edges: j in [j0, j0+ne). Read cols straight from global
    // (L2-resident after first touch; 8-deep MLP).
    const int j0 = hf * HEDGE;                 // 0 or 8
    const int ne = hf ? (RD - HEDGE) : HEDGE;  // 7 or 8
    int cols[HEDGE];
    #pragma unroll
    for (int jj = 0; jj < HEDGE; jj++)
        cols[jj] = (jj < ne) ? g_cols[row * RD + j0 + jj] : 0;
    cw_bar(half);   // V + fill ready

    // One-time slot assignment (unique slot within each column).
    int slot[HEDGE];
    #pragma unroll
    for (int jj = 0; jj < HEDGE; jj++) {
        if (jj < ne) {
            int q = atomicAdd(&fill[cols[jj]], 1);
            slot[jj] = q * NN + cols[jj];
        }
    }
    cw_bar(half);   // slots + degrees final

    const int cd0 = fill[n0], cd1 = fill[n1];

    float Eprev[HEDGE];
    #pragma unroll
    for (int jj = 0; jj < HEDGE; jj++) Eprev[jj] = 0.0f;

    #pragma unroll
    for (int it = 0; it < ITERS; it++) {
        const float a  = a_[it];
        const float bt = bt_[it];

        // ---- row phase (half): gather, sign XOR, min1/min2 over my edges ----
        float am[HEDGE];
        unsigned sb[HEDGE];
        unsigned sgn = 0u;
        #pragma unroll
        for (int jj = 0; jj < HEDGE; jj++) {
            if (jj < ne) {
                float m = V[cols[jj]] - Eprev[jj];
                sb[jj] = __float_as_uint(m) & 0x80000000u;
                sgn   ^= sb[jj];
                am[jj] = fabsf(m);
            } else {
                sb[jj] = 0u;
                am[jj] = INFINITY;
            }
        }
        // two sub-chains of 4 + merge (first-index tie-break)
        float a1 = INFINITY, a2 = INFINITY; int ja = j0;
        #pragma unroll
        for (int jj = 0; jj < 4; jj++) {
            if (am[jj] < a1) { a2 = a1; a1 = am[jj]; ja = j0 + jj; }
            else if (am[jj] < a2) { a2 = am[jj]; }
        }
        float b1 = INFINITY, b2 = INFINITY; int jb = j0 + 4;
        #pragma unroll
        for (int jj = 4; jj < HEDGE; jj++) {
            if (am[jj] < b1) { b2 = b1; b1 = am[jj]; jb = j0 + jj; }
            else if (am[jj] < b2) { b2 = am[jj]; }
        }
        const bool  tA = (a1 <= b1);
        float min1 = tA ? a1 : b1;
        float min2 = tA ? fminf(a2, b1) : fminf(b2, a1);
        int   jmin = tA ? ja : jb;

        // ---- cross-half merge via shfl_xor(1) (pair shares a warp) ----
        const float o1 = __shfl_xor_sync(0xFFFFFFFFu, min1, 1);
        const float o2 = __shfl_xor_sync(0xFFFFFFFFu, min2, 1);
        const int   oj = __shfl_xor_sync(0xFFFFFFFFu, jmin, 1);
        const unsigned osg = __shfl_xor_sync(0xFFFFFFFFu, sgn, 1);
        const unsigned sgc = sgn ^ osg;
        const bool mine = hf ? (min1 < o1) : (min1 <= o1);   // low index wins ties
        const int   jminc = mine ? jmin : oj;
        const float min1c = mine ? min1 : o1;
        const float min2c = mine ? fminf(min2, o1) : fminf(o2, min1);

        const float mag1 = a * fmaxf(0.0f, min1c - bt);
        const float mag2 = a * fmaxf(0.0f, min2c - bt);

        // ---- emit my edges ----
        #pragma unroll
        for (int jj = 0; jj < HEDGE; jj++) {
            if (jj < ne) {
                float mag = ((j0 + jj) == jminc) ? mag2 : mag1;
                float e = __uint_as_float(__float_as_uint(mag) ^ (sgc ^ sb[jj]));
                Eprev[jj] = e;
                E_sh[slot[jj]] = e;
            }
        }
        cw_bar(half);   // edges published; V reads done

        // ---- column phase: 2 owned columns, conflict-free ----
        float s0 = rc0, s1 = rc1;
        for (int q = 0; q < cd0; q++) s0 += E_sh[q * NN + n0];
        for (int q = 0; q < cd1; q++) s1 += E_sh[q * NN + n1];
        if (it < ITERS - 1) {
            V[n0] = s0;
            V[n1] = s1;
            cw_bar(half);
        } else {
            out[b * NN + n0] = s0;   // coalesced
            out[b * NN + n1] = s1;
        }
    }
}

extern "C" void kernel_launch(void* const* d_in, const int* in_sizes, int n_in,
                              void* d_out, int out_size) {
    const float* r     = (const float*)d_in[0];   // (256, 576)
    const float* H     = (const float*)d_in[1];   // (144, 576)
    const float* alpha = (const float*)d_in[2];   // (3,)
    const float* beta  = (const float*)d_in[3];   // (3,)
    float* out = (float*)d_out;                   // (256, 576)

    cudaFuncSetAttribute(ldpc_decode_kernel,
                         cudaFuncAttributeMaxDynamicSharedMemorySize, SMEM_BYTES);

    ldpc_prep<<<MR, NN>>>(H);
    ldpc_decode_kernel<<<BATCH / CWPB, TPB, SMEM_BYTES>>>(r, alpha, beta, out);
}